// round 3
// baseline (speedup 1.0000x reference)
#include <cuda_runtime.h>
#include <cuda_bf16.h>
#include <cstdint>

#define B 8
#define N 65536
#define C 256
#define NS 1024
#define K1 (C + 3)          // 259
#define M 128
#define EPS 1e-5f

// ---------------- scratch (no allocs allowed; device globals) -------------
__device__ int   d_inds[B][NS];
__device__ float d_g [B][K1][NS];     // concat(xyz-rel, gathered feats)
__device__ float d_y1[B][M][NS];
__device__ float d_y2[B][M][NS];
__device__ float d_y3[B][M][NS];
__device__ float d_scale[3][M];
__device__ float d_shift[3][M];
__device__ float d_f[B][M];

// Compile-time buffer selection INSIDE device code (host must never take
// addresses of __device__ globals — that yields the host shadow symbol,
// which ATS happily lets the GPU read as zeros).
template<int L> __device__ __forceinline__ const float* layer_in();
template<> __device__ __forceinline__ const float* layer_in<0>() { return &d_g [0][0][0]; }
template<> __device__ __forceinline__ const float* layer_in<1>() { return &d_y1[0][0][0]; }
template<> __device__ __forceinline__ const float* layer_in<2>() { return &d_y2[0][0][0]; }
template<int L> __device__ __forceinline__ float* layer_out();
template<> __device__ __forceinline__ float* layer_out<0>() { return &d_y1[0][0][0]; }
template<> __device__ __forceinline__ float* layer_out<1>() { return &d_y2[0][0][0]; }
template<> __device__ __forceinline__ float* layer_out<2>() { return &d_y3[0][0][0]; }

// ---------------- 1) ball query: first NS valid indices, ascending --------
__global__ void ballquery_kernel(const float* __restrict__ xyz) {
    int b = blockIdx.x;
    const float* x = xyz + (size_t)b * N * 3;
    float cx = x[0], cy = x[1], cz = x[2];

    __shared__ int s_base;
    __shared__ int s_wcnt[32];
    int tid = threadIdx.x;          // 1024 threads
    int warp = tid >> 5, lane = tid & 31;
    if (tid == 0) s_base = 0;
    __syncthreads();

    for (int start = 0; start < N && s_base < NS; start += 1024) {
        int i = start + tid;
        float dx = x[i*3+0] - cx;
        float dy = x[i*3+1] - cy;
        float dz = x[i*3+2] - cz;
        bool valid = (dx*dx + dy*dy + dz*dz) < 1.0f;   // RADIUS^2 = 1
        unsigned m = __ballot_sync(0xffffffffu, valid);
        int wpref = __popc(m & ((1u << lane) - 1u));
        if (lane == 0) s_wcnt[warp] = __popc(m);
        __syncthreads();
        int base = s_base;
        if (tid < 32) {
            int v = s_wcnt[tid];
            #pragma unroll
            for (int o = 1; o < 32; o <<= 1) {
                int t = __shfl_up_sync(0xffffffffu, v, o);
                if (tid >= o) v += t;
            }
            s_wcnt[tid] = v;        // inclusive scan
        }
        __syncthreads();
        int woff = (warp == 0) ? 0 : s_wcnt[warp - 1];
        int pos = base + woff + wpref;
        if (valid && pos < NS) d_inds[b][pos] = i;
        int total = s_wcnt[31];
        __syncthreads();
        if (tid == 0) s_base = base + total;
        __syncthreads();
    }

    int count = min(s_base, NS);
    __syncthreads();
    int first = d_inds[b][0];       // index 0 always valid (d2 == 0)
    for (int p = count + tid; p < NS; p += 1024) d_inds[b][p] = first;
    __syncthreads();

    // xyz rows of g (relative to center; RADIUS = 1)
    for (int n = tid; n < NS; n += 1024) {
        int id = d_inds[b][n];
        d_g[b][0][n] = x[id*3+0] - cx;
        d_g[b][1][n] = x[id*3+1] - cy;
        d_g[b][2][n] = x[id*3+2] - cz;
    }
}

// ---------------- 2) feature gather --------------------------------------
__global__ void gather_kernel(const float* __restrict__ feat) {
    int c = blockIdx.x;             // 0..255
    int b = blockIdx.y;
    const float* fp = feat + ((size_t)b * C + c) * N;
    for (int n = threadIdx.x; n < NS; n += blockDim.x) {
        d_g[b][3 + c][n] = __ldg(fp + d_inds[b][n]);
    }
}

// ---------------- 3) GEMM: Y[b,o,n] = sum_k W[o,k]*X'[b,k,n] + bias[o] ----
// LAYER selects in/out scratch; for LAYER>0 the operand load fuses the
// previous layer's BN+ReLU via d_scale/d_shift[LAYER-1].
template<int K, int LAYER>
__global__ void gemm_kernel(const float* __restrict__ W,
                            const float* __restrict__ bias) {
    constexpr int NT = 64, KT = 8;
    __shared__ float As[KT][M];     // W[k][m]
    __shared__ float Bs[KT][NT];
    int b  = blockIdx.y;
    int n0 = blockIdx.x * NT;
    int tid = threadIdx.x;          // 256
    int tm = (tid & 15) * 8;        // 8 M-rows
    int tn = (tid >> 4) * 4;        // 4 N-cols
    float acc[8][4] = {};
    const float* Xb = layer_in<LAYER>() + (size_t)b * K * NS;

    for (int k0 = 0; k0 < K; k0 += KT) {
        #pragma unroll
        for (int j = 0; j < 4; j++) {           // 1024 A elems
            int idx = tid + 256 * j;
            int m = idx & 127, kk = idx >> 7;
            int k = k0 + kk;
            As[kk][m] = (k < K) ? W[m * K + k] : 0.f;
        }
        #pragma unroll
        for (int j = 0; j < 2; j++) {           // 512 B elems
            int idx = tid + 256 * j;
            int n = idx & 63, kk = idx >> 6;
            int k = k0 + kk;
            float v = 0.f;
            if (k < K) {
                v = Xb[(size_t)k * NS + n0 + n];
                if (LAYER > 0)
                    v = fmaxf(fmaf(d_scale[LAYER-1][k], v, d_shift[LAYER-1][k]), 0.f);
            }
            Bs[kk][n] = v;
        }
        __syncthreads();
        #pragma unroll
        for (int kk = 0; kk < KT; kk++) {
            float a[8], bb[4];
            #pragma unroll
            for (int i = 0; i < 8; i++) a[i] = As[kk][tm + i];
            #pragma unroll
            for (int j = 0; j < 4; j++) bb[j] = Bs[kk][tn + j];
            #pragma unroll
            for (int i = 0; i < 8; i++)
                #pragma unroll
                for (int j = 0; j < 4; j++)
                    acc[i][j] = fmaf(a[i], bb[j], acc[i][j]);
        }
        __syncthreads();
    }

    float* Yb = layer_out<LAYER>() + (size_t)b * M * NS;
    #pragma unroll
    for (int i = 0; i < 8; i++) {
        float bi = bias[tm + i];
        #pragma unroll
        for (int j = 0; j < 4; j++)
            Yb[(size_t)(tm + i) * NS + n0 + tn + j] = acc[i][j] + bi;
    }
}

// ---------------- 4) BN stats over (B, NS) per channel --------------------
template<int LAYER>
__global__ void stats_kernel(const float* __restrict__ gamma,
                             const float* __restrict__ beta) {
    int c = blockIdx.x;             // 0..127
    int tid = threadIdx.x;          // 256
    const float* Y = layer_out<LAYER>();
    float s = 0.f, s2 = 0.f;
    for (int b = 0; b < B; b++) {
        const float* p = Y + ((size_t)b * M + c) * NS;
        for (int n = tid; n < NS; n += 256) {
            float v = p[n];
            s += v; s2 += v * v;
        }
    }
    __shared__ float rs[8], rs2[8];
    #pragma unroll
    for (int o = 16; o; o >>= 1) {
        s  += __shfl_down_sync(0xffffffffu, s,  o);
        s2 += __shfl_down_sync(0xffffffffu, s2, o);
    }
    if ((tid & 31) == 0) { rs[tid >> 5] = s; rs2[tid >> 5] = s2; }
    __syncthreads();
    if (tid == 0) {
        s = 0.f; s2 = 0.f;
        for (int w = 0; w < 8; w++) { s += rs[w]; s2 += rs2[w]; }
        float inv = 1.0f / (float)(B * NS);
        float mn = s * inv;
        float var = s2 * inv - mn * mn;
        float a = gamma[c] * rsqrtf(var + EPS);
        d_scale[LAYER][c] = a;
        d_shift[LAYER][c] = beta[c] - mn * a;
    }
}

// ---------------- 5) fused BN3 + ReLU + max over n ------------------------
__global__ void maxpool_kernel() {
    int c = blockIdx.x, b = blockIdx.y;
    int tid = threadIdx.x;          // 128
    const float* p = &d_y3[b][c][0];
    float a = d_scale[2][c], d = d_shift[2][c];
    float mx = -1e30f;
    for (int n = tid; n < NS; n += 128)
        mx = fmaxf(mx, fmaf(a, p[n], d));
    #pragma unroll
    for (int o = 16; o; o >>= 1)
        mx = fmaxf(mx, __shfl_down_sync(0xffffffffu, mx, o));
    __shared__ float rm[4];
    if ((tid & 31) == 0) rm[tid >> 5] = mx;
    __syncthreads();
    if (tid == 0) {
        mx = fmaxf(fmaxf(rm[0], rm[1]), fmaxf(rm[2], rm[3]));
        d_f[b][c] = fmaxf(mx, 0.f);
    }
}

// ---------------- 6) FC head (single block) -------------------------------
__global__ void head_kernel(const float* __restrict__ xyz,
                            const float* __restrict__ hw1, const float* __restrict__ hb1,
                            const float* __restrict__ hg1, const float* __restrict__ hbe1,
                            const float* __restrict__ hw2, const float* __restrict__ hb2,
                            const float* __restrict__ hg2, const float* __restrict__ hbe2,
                            const float* __restrict__ hw3, const float* __restrict__ hb3,
                            float* __restrict__ out) {
    __shared__ float sf[B][M];
    __shared__ float z [B][M];
    __shared__ float sa[M], sb_[M];
    int tid = threadIdx.x;          // 1024
    int b = tid >> 7, o = tid & 127;
    sf[b][o] = d_f[b][o];
    __syncthreads();

    // layer 1
    {
        float acc = hb1[o];
        #pragma unroll 8
        for (int k = 0; k < M; k++) acc = fmaf(sf[b][k], hw1[o * M + k], acc);
        z[b][o] = acc;
    }
    __syncthreads();
    if (tid < M) {
        float s = 0.f, s2 = 0.f;
        for (int bb = 0; bb < B; bb++) { float v = z[bb][tid]; s += v; s2 += v * v; }
        float mn = s * 0.125f, var = s2 * 0.125f - mn * mn;
        float a = hg1[tid] * rsqrtf(var + EPS);
        sa[tid] = a; sb_[tid] = hbe1[tid] - mn * a;
    }
    __syncthreads();
    sf[b][o] = fmaxf(fmaf(sa[o], z[b][o], sb_[o]), 0.f);
    __syncthreads();

    // layer 2
    {
        float acc = hb2[o];
        #pragma unroll 8
        for (int k = 0; k < M; k++) acc = fmaf(sf[b][k], hw2[o * M + k], acc);
        z[b][o] = acc;
    }
    __syncthreads();
    if (tid < M) {
        float s = 0.f, s2 = 0.f;
        for (int bb = 0; bb < B; bb++) { float v = z[bb][tid]; s += v; s2 += v * v; }
        float mn = s * 0.125f, var = s2 * 0.125f - mn * mn;
        float a = hg2[tid] * rsqrtf(var + EPS);
        sa[tid] = a; sb_[tid] = hbe2[tid] - mn * a;
    }
    __syncthreads();
    sf[b][o] = fmaxf(fmaf(sa[o], z[b][o], sb_[o]), 0.f);
    __syncthreads();

    // layer 3: 8 x 12 outputs
    if (tid < B * 12) {
        int bb = tid / 12, oo = tid % 12;
        float acc = hb3[oo];
        #pragma unroll 8
        for (int k = 0; k < M; k++) acc = fmaf(sf[bb][k], hw3[oo * M + k], acc);
        if (oo < 3)      out[bb * 3 + oo]            = xyz[(size_t)bb * N * 3 + oo] + acc;  // center_out
        else if (oo < 6) out[24 + bb * 3 + (oo - 3)] = acc;                                  // size
        else             out[48 + bb * 6 + (oo - 6)] = acc;                                  // rot_6d
    }
}

// ---------------- launch ---------------------------------------------------
extern "C" void kernel_launch(void* const* d_in, const int* in_sizes, int n_in,
                              void* d_out, int out_size) {
    const float* xyz  = (const float*)d_in[0];
    const float* feat = (const float*)d_in[1];
    const float* w1   = (const float*)d_in[2];
    const float* b1   = (const float*)d_in[3];
    const float* g1   = (const float*)d_in[4];
    const float* be1  = (const float*)d_in[5];
    const float* w2   = (const float*)d_in[6];
    const float* b2   = (const float*)d_in[7];
    const float* g2   = (const float*)d_in[8];
    const float* be2  = (const float*)d_in[9];
    const float* w3   = (const float*)d_in[10];
    const float* b3   = (const float*)d_in[11];
    const float* g3   = (const float*)d_in[12];
    const float* be3  = (const float*)d_in[13];
    const float* hw1  = (const float*)d_in[14];
    const float* hb1  = (const float*)d_in[15];
    const float* hg1  = (const float*)d_in[16];
    const float* hbe1 = (const float*)d_in[17];
    const float* hw2  = (const float*)d_in[18];
    const float* hb2  = (const float*)d_in[19];
    const float* hg2  = (const float*)d_in[20];
    const float* hbe2 = (const float*)d_in[21];
    const float* hw3  = (const float*)d_in[22];
    const float* hb3  = (const float*)d_in[23];
    float* out = (float*)d_out;

    ballquery_kernel<<<B, 1024>>>(xyz);
    gather_kernel<<<dim3(C, B), 256>>>(feat);

    gemm_kernel<K1, 0><<<dim3(NS / 64, B), 256>>>(w1, b1);
    stats_kernel<0><<<M, 256>>>(g1, be1);

    gemm_kernel<M, 1><<<dim3(NS / 64, B), 256>>>(w2, b2);
    stats_kernel<1><<<M, 256>>>(g2, be2);

    gemm_kernel<M, 2><<<dim3(NS / 64, B), 256>>>(w3, b3);
    stats_kernel<2><<<M, 256>>>(g3, be3);

    maxpool_kernel<<<dim3(M, B), 128>>>();

    head_kernel<<<1, 1024>>>(xyz, hw1, hb1, hg1, hbe1, hw2, hb2, hg2, hbe2, hw3, hb3, out);
}

// round 4
// speedup vs baseline: 1.2028x; 1.2028x over previous
#include <cuda_runtime.h>
#include <cuda_bf16.h>
#include <cstdint>

#define B 8
#define N 65536
#define C 256
#define NS 1024
#define K1 259              // real K of layer 1
#define KP 272              // padded K (multiple of 16)
#define M 128
#define EPS 1e-5f

// ---------------- scratch (device globals; no allocs) ---------------------
__device__ __align__(256) int      d_inds[B][NS];
__device__ __align__(256) float    d_g [B][KP][NS];    // rows 0-2 xyz, 3-258 feat, 259-271 zero
__device__ __align__(256) float    d_y1[B][M][NS];
__device__ __align__(256) float    d_y2[B][M][NS];
__device__ __align__(256) float    d_wT1[KP][M];
__device__ __align__(256) float    d_wT2[M][M];
__device__ __align__(256) float    d_wT3[M][M];
__device__ __align__(256) float    d_sum [3][M];
__device__ __align__(256) float    d_sum2[3][M];
__device__ __align__(256) unsigned d_maxenc[B][M];
__device__ __align__(256) unsigned d_minenc[B][M];

// device-side buffer selection (NEVER take __device__ addresses host-side!)
template<int L> __device__ __forceinline__ const float* layer_in();
template<> __device__ __forceinline__ const float* layer_in<0>() { return &d_g [0][0][0]; }
template<> __device__ __forceinline__ const float* layer_in<1>() { return &d_y1[0][0][0]; }
template<> __device__ __forceinline__ const float* layer_in<2>() { return &d_y2[0][0][0]; }
template<int L> __device__ __forceinline__ float* layer_out();
template<> __device__ __forceinline__ float* layer_out<0>() { return &d_y1[0][0][0]; }
template<> __device__ __forceinline__ float* layer_out<1>() { return &d_y2[0][0][0]; }
template<> __device__ __forceinline__ float* layer_out<2>() { return nullptr; }   // y3 never stored
template<int L> __device__ __forceinline__ const float* wT();
template<> __device__ __forceinline__ const float* wT<0>() { return &d_wT1[0][0]; }
template<> __device__ __forceinline__ const float* wT<1>() { return &d_wT2[0][0]; }
template<> __device__ __forceinline__ const float* wT<2>() { return &d_wT3[0][0]; }

// order-preserving float<->uint encoding (for atomicMax/Min on floats)
__device__ __forceinline__ unsigned enc(float f) {
    unsigned u = __float_as_uint(f);
    return (u & 0x80000000u) ? ~u : (u | 0x80000000u);
}
__device__ __forceinline__ float dec(unsigned u) {
    return __uint_as_float((u & 0x80000000u) ? (u ^ 0x80000000u) : ~u);
}

// ---------------- 0) prep: zero accumulators, pad rows, transpose weights --
__global__ void prep_kernel(const float* __restrict__ w1,
                            const float* __restrict__ w2,
                            const float* __restrict__ w3) {
    int gtid = blockIdx.x * blockDim.x + threadIdx.x;
    int nthr = gridDim.x * blockDim.x;
    // zero stat accumulators
    for (int i = gtid; i < 3 * M; i += nthr) { (&d_sum[0][0])[i] = 0.f; (&d_sum2[0][0])[i] = 0.f; }
    // init max/min encodings
    for (int i = gtid; i < B * M; i += nthr) { (&d_maxenc[0][0])[i] = 0u; (&d_minenc[0][0])[i] = 0xFFFFFFFFu; }
    // zero padding rows of d_g (k = 259..271)
    for (int i = gtid; i < B * (KP - K1) * NS; i += nthr) {
        int b = i / ((KP - K1) * NS);
        int r = i % ((KP - K1) * NS);
        d_g[b][K1 + r / NS][r % NS] = 0.f;
    }
    // transpose w1 (128 x 259 -> 272 x 128, zero-padded)
    for (int i = gtid; i < KP * M; i += nthr) {
        int k = i / M, m = i % M;
        d_wT1[k][m] = (k < K1) ? w1[m * K1 + k] : 0.f;
    }
    // transpose w2, w3 (128 x 128)
    for (int i = gtid; i < M * M; i += nthr) {
        int k = i / M, m = i % M;
        d_wT2[k][m] = w2[m * M + k];
        d_wT3[k][m] = w3[m * M + k];
    }
}

// ---------------- 1) ball query: first NS valid indices, ascending --------
__global__ void ballquery_kernel(const float* __restrict__ xyz) {
    int b = blockIdx.x;
    const float* x = xyz + (size_t)b * N * 3;
    float cx = x[0], cy = x[1], cz = x[2];

    __shared__ int s_base;
    __shared__ int s_wcnt[32];
    int tid = threadIdx.x;          // 1024 threads
    int warp = tid >> 5, lane = tid & 31;
    if (tid == 0) s_base = 0;
    __syncthreads();

    for (int start = 0; start < N && s_base < NS; start += 1024) {
        int i = start + tid;
        float dx = x[i*3+0] - cx;
        float dy = x[i*3+1] - cy;
        float dz = x[i*3+2] - cz;
        bool valid = (dx*dx + dy*dy + dz*dz) < 1.0f;   // RADIUS^2 = 1
        unsigned m = __ballot_sync(0xffffffffu, valid);
        int wpref = __popc(m & ((1u << lane) - 1u));
        if (lane == 0) s_wcnt[warp] = __popc(m);
        __syncthreads();
        int base = s_base;
        if (tid < 32) {
            int v = s_wcnt[tid];
            #pragma unroll
            for (int o = 1; o < 32; o <<= 1) {
                int t = __shfl_up_sync(0xffffffffu, v, o);
                if (tid >= o) v += t;
            }
            s_wcnt[tid] = v;        // inclusive scan
        }
        __syncthreads();
        int woff = (warp == 0) ? 0 : s_wcnt[warp - 1];
        int pos = base + woff + wpref;
        if (valid && pos < NS) d_inds[b][pos] = i;
        int total = s_wcnt[31];
        __syncthreads();
        if (tid == 0) s_base = base + total;
        __syncthreads();
    }

    int count = min(s_base, NS);
    __syncthreads();
    int first = d_inds[b][0];       // index 0 always valid (d2 == 0)
    for (int p = count + tid; p < NS; p += 1024) d_inds[b][p] = first;
    __syncthreads();

    for (int n = tid; n < NS; n += 1024) {
        int id = d_inds[b][n];
        d_g[b][0][n] = x[id*3+0] - cx;
        d_g[b][1][n] = x[id*3+1] - cy;
        d_g[b][2][n] = x[id*3+2] - cz;
    }
}

// ---------------- 2) feature gather --------------------------------------
__global__ void gather_kernel(const float* __restrict__ feat) {
    int c = blockIdx.x;             // 0..255
    int b = blockIdx.y;
    const float* fp = feat + ((size_t)b * C + c) * N;
    for (int n = threadIdx.x; n < NS; n += blockDim.x) {
        d_g[b][3 + c][n] = __ldg(fp + d_inds[b][n]);
    }
}

// ---------------- 3) fused GEMM + BN-prev + stats(+max) -------------------
// Y[b,o,n] = sum_k W[o,k] * X'[b,k,n] + bias[o],  X' = relu(sc*X+sh) if LAYER>0.
// Epilogue: per-channel sum/sum^2 atomics; LAYER==2 also per-(b,c) max/min,
// and skips the Y store entirely.
template<int K, int LAYER>
__global__ void __launch_bounds__(256)
gemm_kernel(const float* __restrict__ bias,
            const float* __restrict__ gamma_prev,
            const float* __restrict__ beta_prev) {
    constexpr int NT = 64, KT = 16;
    __shared__ float As[KT][M];        // 8KB
    __shared__ float Bs[KT][NT];       // 4KB
    __shared__ float red [16][M + 1];  // n-group partials
    __shared__ float red2[16][M + 1];
    __shared__ float s_scale[M], s_shift[M];

    int b  = blockIdx.y;
    int n0 = blockIdx.x * NT;
    int tid = threadIdx.x;             // 256
    int tm = (tid & 15) * 8;
    int tn = (tid >> 4) * 4;
    int g  = tid >> 4;

    if (LAYER > 0) {                   // finalize previous layer's BN affine
        if (tid < M) {
            float inv = 1.0f / (float)(B * NS);
            float mn  = d_sum [LAYER-1][tid] * inv;
            float var = d_sum2[LAYER-1][tid] * inv - mn * mn;
            float a = gamma_prev[tid] * rsqrtf(var + EPS);
            s_scale[tid] = a;
            s_shift[tid] = beta_prev[tid] - mn * a;
        }
        __syncthreads();
    }

    float acc[8][4] = {};
    const float* Xb = layer_in<LAYER>() + (size_t)b * K * NS;
    const float* Wt = wT<LAYER>();

    int bkk = tid >> 4;                // B-load row
    int bn4 = (tid & 15) * 4;          // B-load col (float4)

    for (int k0 = 0; k0 < K; k0 += KT) {
        // A: KT x 128 = 512 float4, 2 per thread, coalesced from wT
        #pragma unroll
        for (int j = 0; j < 2; j++) {
            int idx = tid + 256 * j;
            int kk = idx >> 5, m4 = (idx & 31) * 4;
            *(float4*)&As[kk][m4] = *(const float4*)&Wt[(k0 + kk) * M + m4];
        }
        // B: KT x NT = 256 float4, 1 per thread, with fused BN+ReLU
        {
            float4 v = *(const float4*)&Xb[(size_t)(k0 + bkk) * NS + n0 + bn4];
            if (LAYER > 0) {
                float a = s_scale[k0 + bkk], h = s_shift[k0 + bkk];
                v.x = fmaxf(fmaf(a, v.x, h), 0.f);
                v.y = fmaxf(fmaf(a, v.y, h), 0.f);
                v.z = fmaxf(fmaf(a, v.z, h), 0.f);
                v.w = fmaxf(fmaf(a, v.w, h), 0.f);
            }
            *(float4*)&Bs[bkk][bn4] = v;
        }
        __syncthreads();
        #pragma unroll
        for (int kk = 0; kk < KT; kk++) {
            float4 a0 = *(float4*)&As[kk][tm];
            float4 a1 = *(float4*)&As[kk][tm + 4];
            float4 bb = *(float4*)&Bs[kk][tn];
            float av[8] = {a0.x,a0.y,a0.z,a0.w,a1.x,a1.y,a1.z,a1.w};
            float bv[4] = {bb.x,bb.y,bb.z,bb.w};
            #pragma unroll
            for (int i = 0; i < 8; i++)
                #pragma unroll
                for (int j = 0; j < 4; j++)
                    acc[i][j] = fmaf(av[i], bv[j], acc[i][j]);
        }
        __syncthreads();
    }

    // ---- epilogue: bias add, optional store, channel stats, optional max --
    float* Yb = (LAYER < 2) ? layer_out<LAYER>() + (size_t)b * M * NS : nullptr;
    float rmax[8], rmin[8];
    #pragma unroll
    for (int i = 0; i < 8; i++) {
        float bi = bias[tm + i];
        float s = 0.f, s2 = 0.f, mx = -3.0e38f, mnv = 3.0e38f;
        #pragma unroll
        for (int j = 0; j < 4; j++) {
            float v = acc[i][j] + bi;
            acc[i][j] = v;
            s += v; s2 += v * v;
            mx = fmaxf(mx, v); mnv = fminf(mnv, v);
        }
        if (LAYER < 2)
            *(float4*)&Yb[(size_t)(tm + i) * NS + n0 + tn] =
                make_float4(acc[i][0], acc[i][1], acc[i][2], acc[i][3]);
        red [g][tm + i] = s;
        red2[g][tm + i] = s2;
        rmax[i] = mx; rmin[i] = mnv;
    }
    __syncthreads();
    if (tid < M) {
        float s = 0.f, s2 = 0.f;
        #pragma unroll
        for (int gg = 0; gg < 16; gg++) { s += red[gg][tid]; s2 += red2[gg][tid]; }
        atomicAdd(&d_sum [LAYER][tid], s);
        atomicAdd(&d_sum2[LAYER][tid], s2);
    }
    if (LAYER == 2) {
        __syncthreads();
        #pragma unroll
        for (int i = 0; i < 8; i++) { red[g][tm + i] = rmax[i]; red2[g][tm + i] = rmin[i]; }
        __syncthreads();
        if (tid < M) {
            float mx = -3.0e38f, mnv = 3.0e38f;
            #pragma unroll
            for (int gg = 0; gg < 16; gg++) { mx = fmaxf(mx, red[gg][tid]); mnv = fminf(mnv, red2[gg][tid]); }
            atomicMax(&d_maxenc[b][tid], enc(mx));
            atomicMin(&d_minenc[b][tid], enc(mnv));
        }
    }
}

// ---------------- 4) FC head (single block): BN3 finalize + maxpool + MLP --
__global__ void head_kernel(const float* __restrict__ xyz,
                            const float* __restrict__ g3,  const float* __restrict__ be3,
                            const float* __restrict__ hw1, const float* __restrict__ hb1,
                            const float* __restrict__ hg1, const float* __restrict__ hbe1,
                            const float* __restrict__ hw2, const float* __restrict__ hb2,
                            const float* __restrict__ hg2, const float* __restrict__ hbe2,
                            const float* __restrict__ hw3, const float* __restrict__ hb3,
                            float* __restrict__ out) {
    __shared__ float sf[B][M];
    __shared__ float z [B][M];
    __shared__ float sa[M], sb_[M];
    int tid = threadIdx.x;          // 1024
    int b = tid >> 7, o = tid & 127;

    if (tid < M) {                  // finalize BN3 affine
        float inv = 1.0f / (float)(B * NS);
        float mn  = d_sum [2][tid] * inv;
        float var = d_sum2[2][tid] * inv - mn * mn;
        float a = g3[tid] * rsqrtf(var + EPS);
        sa[tid] = a;
        sb_[tid] = be3[tid] - mn * a;
    }
    __syncthreads();
    {   // maxpool via decoded extrema (exact for either sign of gamma)
        float a = sa[o], d = sb_[o];
        float mx = dec(d_maxenc[b][o]);
        float mnv = dec(d_minenc[b][o]);
        float v = (a >= 0.f) ? fmaf(a, mx, d) : fmaf(a, mnv, d);
        sf[b][o] = fmaxf(v, 0.f);
    }
    __syncthreads();

    // layer 1
    {
        float acc = hb1[o];
        #pragma unroll 8
        for (int k = 0; k < M; k++) acc = fmaf(sf[b][k], hw1[o * M + k], acc);
        z[b][o] = acc;
    }
    __syncthreads();
    if (tid < M) {
        float s = 0.f, s2 = 0.f;
        for (int bb = 0; bb < B; bb++) { float v = z[bb][tid]; s += v; s2 += v * v; }
        float mn = s * 0.125f, var = s2 * 0.125f - mn * mn;
        float a = hg1[tid] * rsqrtf(var + EPS);
        sa[tid] = a; sb_[tid] = hbe1[tid] - mn * a;
    }
    __syncthreads();
    sf[b][o] = fmaxf(fmaf(sa[o], z[b][o], sb_[o]), 0.f);
    __syncthreads();

    // layer 2
    {
        float acc = hb2[o];
        #pragma unroll 8
        for (int k = 0; k < M; k++) acc = fmaf(sf[b][k], hw2[o * M + k], acc);
        z[b][o] = acc;
    }
    __syncthreads();
    if (tid < M) {
        float s = 0.f, s2 = 0.f;
        for (int bb = 0; bb < B; bb++) { float v = z[bb][tid]; s += v; s2 += v * v; }
        float mn = s * 0.125f, var = s2 * 0.125f - mn * mn;
        float a = hg2[tid] * rsqrtf(var + EPS);
        sa[tid] = a; sb_[tid] = hbe2[tid] - mn * a;
    }
    __syncthreads();
    sf[b][o] = fmaxf(fmaf(sa[o], z[b][o], sb_[o]), 0.f);
    __syncthreads();

    // layer 3: 8 x 12 outputs
    if (tid < B * 12) {
        int bb = tid / 12, oo = tid % 12;
        float acc = hb3[oo];
        #pragma unroll 8
        for (int k = 0; k < M; k++) acc = fmaf(sf[bb][k], hw3[oo * M + k], acc);
        if (oo < 3)      out[bb * 3 + oo]            = xyz[(size_t)bb * N * 3 + oo] + acc;
        else if (oo < 6) out[24 + bb * 3 + (oo - 3)] = acc;
        else             out[48 + bb * 6 + (oo - 6)] = acc;
    }
}

// ---------------- launch ---------------------------------------------------
extern "C" void kernel_launch(void* const* d_in, const int* in_sizes, int n_in,
                              void* d_out, int out_size) {
    const float* xyz  = (const float*)d_in[0];
    const float* feat = (const float*)d_in[1];
    const float* w1   = (const float*)d_in[2];
    const float* b1   = (const float*)d_in[3];
    const float* g1   = (const float*)d_in[4];
    const float* be1  = (const float*)d_in[5];
    const float* w2   = (const float*)d_in[6];
    const float* b2   = (const float*)d_in[7];
    const float* g2   = (const float*)d_in[8];
    const float* be2  = (const float*)d_in[9];
    const float* w3   = (const float*)d_in[10];
    const float* b3   = (const float*)d_in[11];
    const float* g3   = (const float*)d_in[12];
    const float* be3  = (const float*)d_in[13];
    const float* hw1  = (const float*)d_in[14];
    const float* hb1  = (const float*)d_in[15];
    const float* hg1  = (const float*)d_in[16];
    const float* hbe1 = (const float*)d_in[17];
    const float* hw2  = (const float*)d_in[18];
    const float* hb2  = (const float*)d_in[19];
    const float* hg2  = (const float*)d_in[20];
    const float* hbe2 = (const float*)d_in[21];
    const float* hw3  = (const float*)d_in[22];
    const float* hb3  = (const float*)d_in[23];
    float* out = (float*)d_out;

    prep_kernel<<<64, 256>>>(w1, w2, w3);
    ballquery_kernel<<<B, 1024>>>(xyz);
    gather_kernel<<<dim3(C, B), 256>>>(feat);

    gemm_kernel<KP, 0><<<dim3(NS / 64, B), 256>>>(b1, nullptr, nullptr);
    gemm_kernel<M,  1><<<dim3(NS / 64, B), 256>>>(b2, g1, be1);
    gemm_kernel<M,  2><<<dim3(NS / 64, B), 256>>>(b3, g2, be2);

    head_kernel<<<1, 1024>>>(xyz, g3, be3,
                             hw1, hb1, hg1, hbe1,
                             hw2, hb2, hg2, hbe2, hw3, hb3, out);
}

// round 5
// speedup vs baseline: 1.3275x; 1.1037x over previous
#include <cuda_runtime.h>
#include <cuda_bf16.h>
#include <cstdint>

#define B 8
#define N 65536
#define C 256
#define NS 1024
#define K1 259              // real K of layer 1 (3 xyz + 256 feat)
#define KP 272              // padded K (multiple of 16)
#define M 128
#define MH 64               // M per block (M split in 2)
#define NT 64
#define KT 16
#define EPS 1e-5f

// ---------------- scratch (device globals; no allocs) ---------------------
__device__ __align__(256) int      d_inds[B][NS];
__device__ __align__(256) float    d_gxyz[B][3][NS];
__device__ __align__(256) float    d_y1[B][M][NS];
__device__ __align__(256) float    d_y2[B][M][NS];
__device__ __align__(256) float    d_wT1[KP][M];
__device__ __align__(256) float    d_wT2[M][M];
__device__ __align__(256) float    d_wT3[M][M];
__device__ __align__(256) float    d_sum [3][M];
__device__ __align__(256) float    d_sum2[3][M];
__device__ __align__(256) unsigned d_maxenc[B][M];
__device__ __align__(256) unsigned d_minenc[B][M];

// device-side buffer selection (NEVER take __device__ addresses host-side!)
template<int L> __device__ __forceinline__ const float* layer_in();
template<> __device__ __forceinline__ const float* layer_in<1>() { return &d_y1[0][0][0]; }
template<> __device__ __forceinline__ const float* layer_in<2>() { return &d_y2[0][0][0]; }
template<int L> __device__ __forceinline__ float* layer_out();
template<> __device__ __forceinline__ float* layer_out<0>() { return &d_y1[0][0][0]; }
template<> __device__ __forceinline__ float* layer_out<1>() { return &d_y2[0][0][0]; }
template<int L> __device__ __forceinline__ const float* wT();
template<> __device__ __forceinline__ const float* wT<0>() { return &d_wT1[0][0]; }
template<> __device__ __forceinline__ const float* wT<1>() { return &d_wT2[0][0]; }
template<> __device__ __forceinline__ const float* wT<2>() { return &d_wT3[0][0]; }

// order-preserving float<->uint encoding (for atomicMax/Min on floats)
__device__ __forceinline__ unsigned enc(float f) {
    unsigned u = __float_as_uint(f);
    return (u & 0x80000000u) ? ~u : (u | 0x80000000u);
}
__device__ __forceinline__ float dec(unsigned u) {
    return __uint_as_float((u & 0x80000000u) ? (u ^ 0x80000000u) : ~u);
}

// ---------------- 0) prep: zero accumulators, transpose weights -----------
__global__ void prep_kernel(const float* __restrict__ w1,
                            const float* __restrict__ w2,
                            const float* __restrict__ w3) {
    int gtid = blockIdx.x * blockDim.x + threadIdx.x;
    int nthr = gridDim.x * blockDim.x;
    for (int i = gtid; i < 3 * M; i += nthr) { (&d_sum[0][0])[i] = 0.f; (&d_sum2[0][0])[i] = 0.f; }
    for (int i = gtid; i < B * M; i += nthr) { (&d_maxenc[0][0])[i] = 0u; (&d_minenc[0][0])[i] = 0xFFFFFFFFu; }
    for (int i = gtid; i < KP * M; i += nthr) {
        int k = i / M, m = i % M;
        d_wT1[k][m] = (k < K1) ? w1[m * K1 + k] : 0.f;
    }
    for (int i = gtid; i < M * M; i += nthr) {
        int k = i / M, m = i % M;
        d_wT2[k][m] = w2[m * M + k];
        d_wT3[k][m] = w3[m * M + k];
    }
}

// ---------------- 1) ball query: first NS valid indices, ascending --------
__global__ void ballquery_kernel(const float* __restrict__ xyz) {
    int b = blockIdx.x;
    const float* x = xyz + (size_t)b * N * 3;
    float cx = x[0], cy = x[1], cz = x[2];

    __shared__ int s_base;
    __shared__ int s_wcnt[32];
    int tid = threadIdx.x;          // 1024 threads
    int warp = tid >> 5, lane = tid & 31;
    if (tid == 0) s_base = 0;
    __syncthreads();

    for (int start = 0; start < N && s_base < NS; start += 1024) {
        int i = start + tid;
        float dx = x[i*3+0] - cx;
        float dy = x[i*3+1] - cy;
        float dz = x[i*3+2] - cz;
        bool valid = (dx*dx + dy*dy + dz*dz) < 1.0f;   // RADIUS^2 = 1
        unsigned m = __ballot_sync(0xffffffffu, valid);
        int wpref = __popc(m & ((1u << lane) - 1u));
        if (lane == 0) s_wcnt[warp] = __popc(m);
        __syncthreads();
        int base = s_base;
        if (tid < 32) {
            int v = s_wcnt[tid];
            #pragma unroll
            for (int o = 1; o < 32; o <<= 1) {
                int t = __shfl_up_sync(0xffffffffu, v, o);
                if (tid >= o) v += t;
            }
            s_wcnt[tid] = v;        // inclusive scan
        }
        __syncthreads();
        int woff = (warp == 0) ? 0 : s_wcnt[warp - 1];
        int pos = base + woff + wpref;
        if (valid && pos < NS) d_inds[b][pos] = i;
        int total = s_wcnt[31];
        __syncthreads();
        if (tid == 0) s_base = base + total;
        __syncthreads();
    }

    int count = min(s_base, NS);
    __syncthreads();
    int first = d_inds[b][0];       // index 0 always valid (d2 == 0)
    for (int p = count + tid; p < NS; p += 1024) d_inds[b][p] = first;
    __syncthreads();

    for (int n = tid; n < NS; n += 1024) {
        int id = d_inds[b][n];
        d_gxyz[b][0][n] = x[id*3+0] - cx;
        d_gxyz[b][1][n] = x[id*3+1] - cy;
        d_gxyz[b][2][n] = x[id*3+2] - cz;
    }
}

// ---------------- 2) fused (gather+)GEMM + BN-prev + stats(+max) ----------
// Y[b,o,n] = sum_k W[o,k] * X'[b,k,n] + bias[o]
//   LAYER==0: X gathered on the fly (xyz rows + feat[b][c][inds[n]])
//   LAYER>0 : X' = relu(scale*X + shift) finalized from global stat atomics
//   LAYER==2: no Y store; per-(b,c) running max/min via encoded atomics
template<int K, int LAYER>
__global__ void __launch_bounds__(256)
gemm_kernel(const float* __restrict__ feat,
            const float* __restrict__ bias,
            const float* __restrict__ gamma_prev,
            const float* __restrict__ beta_prev) {
    __shared__ float As[KT][MH];         // 4KB
    __shared__ float Bs[KT][NT];         // 4KB
    __shared__ float red [16][MH + 1];   // 4.06KB
    __shared__ float red2[16][MH + 1];
    __shared__ float s_scale[M], s_shift[M];
    __shared__ int   s_inds[NT];

    int n0 = blockIdx.x * NT;
    int m0 = blockIdx.y * MH;
    int b  = blockIdx.z;
    int tid = threadIdx.x;               // 256
    int tm = (tid & 15) * 4;             // 4 M-rows
    int tn = (tid >> 4) * 4;             // 4 N-cols
    int g  = tid >> 4;                   // n-group for reductions

    if (LAYER == 0) {
        if (tid < NT) s_inds[tid] = d_inds[b][n0 + tid];
    } else {
        if (tid < M) {                   // finalize previous layer's BN affine
            float inv = 1.0f / (float)(B * NS);
            float mn  = d_sum [LAYER-1][tid] * inv;
            float var = d_sum2[LAYER-1][tid] * inv - mn * mn;
            float a = gamma_prev[tid] * rsqrtf(var + EPS);
            s_scale[tid] = a;
            s_shift[tid] = beta_prev[tid] - mn * a;
        }
    }
    __syncthreads();

    float acc[4][4] = {};
    const float* Wt = wT<LAYER>();
    const float* fb = feat + (size_t)b * C * N;

    int bkk = tid >> 4;                  // load row (0..15)
    int bn4 = (tid & 15) * 4;            // load col base

    for (int k0 = 0; k0 < K; k0 += KT) {
        // A: KT x MH = 256 float4 -> 1 per thread (coalesced from wT)
        *(float4*)&As[bkk][bn4] = *(const float4*)&Wt[(k0 + bkk) * M + m0 + bn4];
        // B: KT x NT = 256 float4-equiv -> 1 per thread
        {
            int row = k0 + bkk;
            float4 v;
            if (LAYER == 0) {
                if (row < 3) {
                    v = *(const float4*)&d_gxyz[b][row][n0 + bn4];
                } else if (row < K1) {
                    const float* fr = fb + (size_t)(row - 3) * N;
                    v.x = __ldg(fr + s_inds[bn4 + 0]);
                    v.y = __ldg(fr + s_inds[bn4 + 1]);
                    v.z = __ldg(fr + s_inds[bn4 + 2]);
                    v.w = __ldg(fr + s_inds[bn4 + 3]);
                } else {
                    v = make_float4(0.f, 0.f, 0.f, 0.f);
                }
            } else {
                const float* Xb = layer_in<LAYER>() + (size_t)b * M * NS;
                v = *(const float4*)&Xb[(size_t)row * NS + n0 + bn4];
                float a = s_scale[row], h = s_shift[row];
                v.x = fmaxf(fmaf(a, v.x, h), 0.f);
                v.y = fmaxf(fmaf(a, v.y, h), 0.f);
                v.z = fmaxf(fmaf(a, v.z, h), 0.f);
                v.w = fmaxf(fmaf(a, v.w, h), 0.f);
            }
            *(float4*)&Bs[bkk][bn4] = v;
        }
        __syncthreads();
        #pragma unroll
        for (int kk = 0; kk < KT; kk++) {
            float4 a0 = *(float4*)&As[kk][tm];
            float4 bb = *(float4*)&Bs[kk][tn];
            float av[4] = {a0.x, a0.y, a0.z, a0.w};
            float bv[4] = {bb.x, bb.y, bb.z, bb.w};
            #pragma unroll
            for (int i = 0; i < 4; i++)
                #pragma unroll
                for (int j = 0; j < 4; j++)
                    acc[i][j] = fmaf(av[i], bv[j], acc[i][j]);
        }
        __syncthreads();
    }

    // ---- epilogue: bias add, optional store, channel stats, optional max --
    float* Yb = (LAYER < 2) ? layer_out<(LAYER < 2 ? LAYER : 0)>() + (size_t)b * M * NS : nullptr;
    float rmax[4], rmin[4];
    #pragma unroll
    for (int i = 0; i < 4; i++) {
        float bi = bias[m0 + tm + i];
        float s = 0.f, s2 = 0.f, mx = -3.0e38f, mnv = 3.0e38f;
        #pragma unroll
        for (int j = 0; j < 4; j++) {
            float v = acc[i][j] + bi;
            acc[i][j] = v;
            s += v; s2 += v * v;
            mx = fmaxf(mx, v); mnv = fminf(mnv, v);
        }
        if (LAYER < 2)
            *(float4*)&Yb[(size_t)(m0 + tm + i) * NS + n0 + tn] =
                make_float4(acc[i][0], acc[i][1], acc[i][2], acc[i][3]);
        red [g][tm + i] = s;
        red2[g][tm + i] = s2;
        rmax[i] = mx; rmin[i] = mnv;
    }
    __syncthreads();
    if (tid < MH) {
        float s = 0.f, s2 = 0.f;
        #pragma unroll
        for (int gg = 0; gg < 16; gg++) { s += red[gg][tid]; s2 += red2[gg][tid]; }
        atomicAdd(&d_sum [LAYER][m0 + tid], s);
        atomicAdd(&d_sum2[LAYER][m0 + tid], s2);
    }
    if (LAYER == 2) {
        __syncthreads();
        #pragma unroll
        for (int i = 0; i < 4; i++) { red[g][tm + i] = rmax[i]; red2[g][tm + i] = rmin[i]; }
        __syncthreads();
        if (tid < MH) {
            float mx = -3.0e38f, mnv = 3.0e38f;
            #pragma unroll
            for (int gg = 0; gg < 16; gg++) { mx = fmaxf(mx, red[gg][tid]); mnv = fminf(mnv, red2[gg][tid]); }
            atomicMax(&d_maxenc[b][m0 + tid], enc(mx));
            atomicMin(&d_minenc[b][m0 + tid], enc(mnv));
        }
    }
}

// ---------------- 3) FC head (single block): BN3 finalize + maxpool + MLP --
__global__ void head_kernel(const float* __restrict__ xyz,
                            const float* __restrict__ g3,  const float* __restrict__ be3,
                            const float* __restrict__ hw1, const float* __restrict__ hb1,
                            const float* __restrict__ hg1, const float* __restrict__ hbe1,
                            const float* __restrict__ hw2, const float* __restrict__ hb2,
                            const float* __restrict__ hg2, const float* __restrict__ hbe2,
                            const float* __restrict__ hw3, const float* __restrict__ hb3,
                            float* __restrict__ out) {
    __shared__ float sf[B][M];
    __shared__ float z [B][M];
    __shared__ float sa[M], sb_[M];
    int tid = threadIdx.x;          // 1024
    int b = tid >> 7, o = tid & 127;

    if (tid < M) {                  // finalize BN3 affine
        float inv = 1.0f / (float)(B * NS);
        float mn  = d_sum [2][tid] * inv;
        float var = d_sum2[2][tid] * inv - mn * mn;
        float a = g3[tid] * rsqrtf(var + EPS);
        sa[tid] = a;
        sb_[tid] = be3[tid] - mn * a;
    }
    __syncthreads();
    {   // maxpool via decoded extrema (exact for either sign of gamma)
        float a = sa[o], d = sb_[o];
        float mx = dec(d_maxenc[b][o]);
        float mnv = dec(d_minenc[b][o]);
        float v = (a >= 0.f) ? fmaf(a, mx, d) : fmaf(a, mnv, d);
        sf[b][o] = fmaxf(v, 0.f);
    }
    __syncthreads();

    // layer 1
    {
        float acc = hb1[o];
        #pragma unroll 8
        for (int k = 0; k < M; k++) acc = fmaf(sf[b][k], hw1[o * M + k], acc);
        z[b][o] = acc;
    }
    __syncthreads();
    if (tid < M) {
        float s = 0.f, s2 = 0.f;
        for (int bb = 0; bb < B; bb++) { float v = z[bb][tid]; s += v; s2 += v * v; }
        float mn = s * 0.125f, var = s2 * 0.125f - mn * mn;
        float a = hg1[tid] * rsqrtf(var + EPS);
        sa[tid] = a; sb_[tid] = hbe1[tid] - mn * a;
    }
    __syncthreads();
    sf[b][o] = fmaxf(fmaf(sa[o], z[b][o], sb_[o]), 0.f);
    __syncthreads();

    // layer 2
    {
        float acc = hb2[o];
        #pragma unroll 8
        for (int k = 0; k < M; k++) acc = fmaf(sf[b][k], hw2[o * M + k], acc);
        z[b][o] = acc;
    }
    __syncthreads();
    if (tid < M) {
        float s = 0.f, s2 = 0.f;
        for (int bb = 0; bb < B; bb++) { float v = z[bb][tid]; s += v; s2 += v * v; }
        float mn = s * 0.125f, var = s2 * 0.125f - mn * mn;
        float a = hg2[tid] * rsqrtf(var + EPS);
        sa[tid] = a; sb_[tid] = hbe2[tid] - mn * a;
    }
    __syncthreads();
    sf[b][o] = fmaxf(fmaf(sa[o], z[b][o], sb_[o]), 0.f);
    __syncthreads();

    // layer 3: 8 x 12 outputs
    if (tid < B * 12) {
        int bb = tid / 12, oo = tid % 12;
        float acc = hb3[oo];
        #pragma unroll 8
        for (int k = 0; k < M; k++) acc = fmaf(sf[bb][k], hw3[oo * M + k], acc);
        if (oo < 3)      out[bb * 3 + oo]            = xyz[(size_t)bb * N * 3 + oo] + acc;
        else if (oo < 6) out[24 + bb * 3 + (oo - 3)] = acc;
        else             out[48 + bb * 6 + (oo - 6)] = acc;
    }
}

// ---------------- launch ---------------------------------------------------
extern "C" void kernel_launch(void* const* d_in, const int* in_sizes, int n_in,
                              void* d_out, int out_size) {
    const float* xyz  = (const float*)d_in[0];
    const float* feat = (const float*)d_in[1];
    const float* w1   = (const float*)d_in[2];
    const float* b1   = (const float*)d_in[3];
    const float* g1   = (const float*)d_in[4];
    const float* be1  = (const float*)d_in[5];
    const float* w2   = (const float*)d_in[6];
    const float* b2   = (const float*)d_in[7];
    const float* g2   = (const float*)d_in[8];
    const float* be2  = (const float*)d_in[9];
    const float* w3   = (const float*)d_in[10];
    const float* b3   = (const float*)d_in[11];
    const float* g3   = (const float*)d_in[12];
    const float* be3  = (const float*)d_in[13];
    const float* hw1  = (const float*)d_in[14];
    const float* hb1  = (const float*)d_in[15];
    const float* hg1  = (const float*)d_in[16];
    const float* hbe1 = (const float*)d_in[17];
    const float* hw2  = (const float*)d_in[18];
    const float* hb2  = (const float*)d_in[19];
    const float* hg2  = (const float*)d_in[20];
    const float* hbe2 = (const float*)d_in[21];
    const float* hw3  = (const float*)d_in[22];
    const float* hb3  = (const float*)d_in[23];
    float* out = (float*)d_out;

    prep_kernel<<<64, 256>>>(w1, w2, w3);
    ballquery_kernel<<<B, 1024>>>(xyz);

    dim3 gemm_grid(NS / NT, M / MH, B);      // (16, 2, 8) = 256 blocks
    gemm_kernel<KP, 0><<<gemm_grid, 256>>>(feat, b1, nullptr, nullptr);
    gemm_kernel<M,  1><<<gemm_grid, 256>>>(feat, b2, g1, be1);
    gemm_kernel<M,  2><<<gemm_grid, 256>>>(feat, b3, g2, be2);

    head_kernel<<<1, 1024>>>(xyz, g3, be3,
                             hw1, hb1, hg1, hbe1,
                             hw2, hb2, hg2, hbe2, hw3, hb3, out);
}